// round 4
// baseline (speedup 1.0000x reference)
#include <cuda_runtime.h>
#include <cstdint>

#define DEVI __device__ __forceinline__

// Problem constants
static constexpr int B_TOT  = 16384;
static constexpr int F_DIM  = 50;
static constexpr int E_DIM  = 64;
static constexpr int D_DIM  = 128;
static constexpr int FE     = F_DIM * E_DIM;      // 3200 floats per batch

// Kernel config
static constexpr int NTHREADS = 512;              // 16 warps
static constexpr int GRID     = 152;              // 1 CTA per SM on GB300
static constexpr int BPI      = 4;                // batches per iteration
static constexpr int NGI      = B_TOT / BPI;      // 4096 iterations total

// SMEM layout (floats)
static constexpr int TH_STR    = 68;              // Theta row stride (mod 32 == 4 -> conflict-free A frags)
static constexpr int X_STR     = 72;              // X row stride    (mod 32 == 8 -> conflict-free B frags)
static constexpr int K_PAD     = 56;              // F padded to 7 k-steps of 8
static constexpr int XBATCH    = K_PAD * X_STR;   // 4032 floats per batch tile
static constexpr int XBUF      = BPI * XBATCH;    // 16128 floats per buffer
static constexpr int TH_FLOATS = D_DIM * TH_STR;  // 8704
static constexpr int PSUM_OFF  = TH_FLOATS + 2 * XBUF;        // 40960
static constexpr int SMEM_FLOATS = PSUM_OFF + BPI * D_DIM;    // 41472
static constexpr int SMEM_BYTES  = SMEM_FLOATS * 4;           // 165888 B

// ---------------------------------------------------------------------------
DEVI uint32_t smem_u32(const void* p) {
    uint32_t a;
    asm("{ .reg .u64 t; cvta.to.shared.u64 t, %1; cvt.u32.u64 %0, t; }" : "=r"(a) : "l"(p));
    return a;
}
DEVI uint32_t f2tf32(float x) {
    uint32_t u;
    asm("cvt.rna.tf32.f32 %0, %1;" : "=r"(u) : "f"(x));
    return u;
}
DEVI void mma16n8k8(float& c0, float& c1, float& c2, float& c3,
                    uint32_t a0, uint32_t a1, uint32_t a2, uint32_t a3,
                    uint32_t b0, uint32_t b1) {
    asm volatile(
        "mma.sync.aligned.m16n8k8.row.col.f32.tf32.tf32.f32 "
        "{%0,%1,%2,%3}, {%4,%5,%6,%7}, {%8,%9}, {%0,%1,%2,%3};"
        : "+f"(c0), "+f"(c1), "+f"(c2), "+f"(c3)
        : "r"(a0), "r"(a1), "r"(a2), "r"(a3), "r"(b0), "r"(b1));
}
DEVI void cp_async16(uint32_t dst, const void* src) {
    asm volatile("cp.async.cg.shared.global [%0], [%1], 16;" :: "r"(dst), "l"(src));
}
DEVI void cp_commit()  { asm volatile("cp.async.commit_group;" ::: "memory"); }
DEVI void cp_wait1()   { asm volatile("cp.async.wait_group 1;" ::: "memory"); }

// Prefetch 4 batches of X into SMEM buffer `buf` (3200 chunks of 16B)
DEVI void prefetch(uint32_t xs_u32, const float* __restrict__ X, int gi, int buf, int tid) {
    const float* gbase = X + (size_t)gi * BPI * FE;
    const uint32_t dbase = xs_u32 + (uint32_t)(buf * XBUF) * 4u;
#pragma unroll 1
    for (int c = tid; c < BPI * 800; c += NTHREADS) {
        int b   = c / 800;
        int r   = c - b * 800;
        int f   = r >> 4;
        int seg = r & 15;
        const float* src = gbase + b * FE + f * E_DIM + seg * 4;
        uint32_t dst = dbase + (uint32_t)(b * XBATCH + f * X_STR + seg * 4) * 4u;
        cp_async16(dst, src);
    }
}

// ---------------------------------------------------------------------------
__global__ void __launch_bounds__(NTHREADS, 1)
InnerProduct_65429531787441_kernel(const float* __restrict__ X,
                                   const float* __restrict__ Th,
                                   float* __restrict__ out) {
    extern __shared__ float sm[];
    uint32_t* thu = reinterpret_cast<uint32_t*>(sm);          // Theta (tf32 bits)
    float*    xs  = sm + TH_FLOATS;                           // X tiles (2 buffers)
    float*    ps  = sm + PSUM_OFF;                            // partial sums [BPI][128]
    const uint32_t xs_u32 = smem_u32(xs);

    const int tid  = threadIdx.x;
    const int lane = tid & 31;
    const int w    = tid >> 5;
    const int b_l  = w >> 2;          // batch slot 0..3
    const int mh   = (w >> 1) & 1;    // d half: 0 -> d 0..63, 1 -> d 64..127
    const int eh   = w & 1;           // e half: 0 -> e 0..31, 1 -> e 32..63
    const int e_base = eh * 32;

    // Prologue prefetch (iteration 0, buffer 0) before init for overlap
    int gi0 = blockIdx.x;
    prefetch(xs_u32, X, gi0, 0, tid);
    cp_commit();

    // Theta -> SMEM as tf32 (zero-pad f = 50..55)
    for (int i = tid; i < D_DIM * K_PAD; i += NTHREADS) {
        int d = i / K_PAD, f = i - d * K_PAD;
        float v = (f < F_DIM) ? Th[d * F_DIM + f] : 0.f;
        thu[d * TH_STR + f] = f2tf32(v);
    }
    // Zero-pad X rows f = 50..55 in all 8 batch slots (never overwritten later)
    for (int i = tid; i < 8 * 6 * X_STR; i += NTHREADS) {
        int slot = i / (6 * X_STR);
        int r    = i - slot * (6 * X_STR);
        xs[slot * XBATCH + F_DIM * X_STR + r] = 0.f;
    }
    __syncthreads();

    const int lg = lane >> 2;   // 0..7
    const int lq = lane & 3;    // 0..3

    int it = 0;
    for (int gi = gi0; gi < NGI; gi += GRID, ++it) {
        const int buf = it & 1;

        // Prefetch next iteration into the other buffer
        if (gi + GRID < NGI) prefetch(xs_u32, X, gi + GRID, buf ^ 1, tid);
        cp_commit();
        cp_wait1();             // current buffer's group complete
        __syncthreads();

        const float* xb = xs + buf * XBUF + b_l * XBATCH;

        float acc[4][4][4];
#pragma unroll
        for (int mi = 0; mi < 4; mi++)
#pragma unroll
            for (int ni = 0; ni < 4; ni++)
#pragma unroll
                for (int j = 0; j < 4; j++) acc[mi][ni][j] = 0.f;

#pragma unroll
        for (int s = 0; s < 7; s++) {
            const int f0 = 8 * s + lq;
            uint32_t A[4][4];
#pragma unroll
            for (int mi = 0; mi < 4; mi++) {
                const int row = mh * 64 + mi * 16 + lg;
                A[mi][0] = thu[row * TH_STR + f0];
                A[mi][1] = thu[(row + 8) * TH_STR + f0];
                A[mi][2] = thu[row * TH_STR + f0 + 4];
                A[mi][3] = thu[(row + 8) * TH_STR + f0 + 4];
            }
            uint32_t Bf[4][2];
#pragma unroll
            for (int ni = 0; ni < 4; ni++) {
                const int e = e_base + ni * 8 + lg;
                Bf[ni][0] = f2tf32(xb[f0 * X_STR + e]);
                Bf[ni][1] = f2tf32(xb[(f0 + 4) * X_STR + e]);
            }
#pragma unroll
            for (int mi = 0; mi < 4; mi++)
#pragma unroll
                for (int ni = 0; ni < 4; ni++)
                    mma16n8k8(acc[mi][ni][0], acc[mi][ni][1], acc[mi][ni][2], acc[mi][ni][3],
                              A[mi][0], A[mi][1], A[mi][2], A[mi][3],
                              Bf[ni][0], Bf[ni][1]);
        }

        // Epilogue: sum of squares over this warp's 32 e-columns
        float slo[4], shi[4];
#pragma unroll
        for (int mi = 0; mi < 4; mi++) {
            float a = 0.f, b = 0.f;
#pragma unroll
            for (int ni = 0; ni < 4; ni++) {
                a = fmaf(acc[mi][ni][0], acc[mi][ni][0], a);
                a = fmaf(acc[mi][ni][1], acc[mi][ni][1], a);
                b = fmaf(acc[mi][ni][2], acc[mi][ni][2], b);
                b = fmaf(acc[mi][ni][3], acc[mi][ni][3], b);
            }
            a += __shfl_xor_sync(0xffffffffu, a, 1);
            a += __shfl_xor_sync(0xffffffffu, a, 2);
            b += __shfl_xor_sync(0xffffffffu, b, 1);
            b += __shfl_xor_sync(0xffffffffu, b, 2);
            slo[mi] = a; shi[mi] = b;
        }

        // Combine the two e-halves via SMEM partials, then store
        if (eh == 0 && lq == 0) {
#pragma unroll
            for (int mi = 0; mi < 4; mi++) {
                const int d = mh * 64 + mi * 16 + lg;
                ps[b_l * D_DIM + d]     = slo[mi];
                ps[b_l * D_DIM + d + 8] = shi[mi];
            }
        }
        __syncthreads();
        if (eh == 1 && lq == 0) {
            float* orow = out + (size_t)(gi * BPI + b_l) * D_DIM;
#pragma unroll
            for (int mi = 0; mi < 4; mi++) {
                const int d = mh * 64 + mi * 16 + lg;
                orow[d]     = slo[mi] + ps[b_l * D_DIM + d];
                orow[d + 8] = shi[mi] + ps[b_l * D_DIM + d + 8];
            }
        }
        __syncthreads();   // protect psum + X buffer before next iteration
    }
}

extern "C" void kernel_launch(void* const* d_in, const int* in_sizes, int n_in,
                              void* d_out, int out_size) {
    (void)in_sizes; (void)n_in; (void)out_size;
    const float* X  = (const float*)d_in[0];
    const float* Th = (const float*)d_in[1];
    float* out = (float*)d_out;
    cudaFuncSetAttribute(InnerProduct_65429531787441_kernel,
                         cudaFuncAttributeMaxDynamicSharedMemorySize, SMEM_BYTES);
    InnerProduct_65429531787441_kernel<<<GRID, NTHREADS, SMEM_BYTES>>>(X, Th, out);
}

// round 6
// speedup vs baseline: 1.6699x; 1.6699x over previous
#include <cuda_runtime.h>
#include <cstdint>

#define DEVI __device__ __forceinline__

// Problem constants
static constexpr int B_TOT  = 16384;
static constexpr int F_DIM  = 50;
static constexpr int E_DIM  = 64;
static constexpr int D_DIM  = 128;
static constexpr int FE     = F_DIM * E_DIM;      // 3200 floats per batch

// Kernel config: 2 CTAs/SM, 256 threads (8 warps), 2 batches per CTA-iteration
static constexpr int NTHREADS = 256;
static constexpr int GRID     = 304;              // 2 CTAs per SM on GB300 (152 SMs)
static constexpr int BPI      = 2;                // batches per iteration
static constexpr int NGI      = B_TOT / BPI;      // 8192 iterations total

// SMEM layout (floats)
static constexpr int K_PAD     = 56;              // F padded to 7 k-steps of 8
static constexpr int X_STR     = 72;              // X row stride (mod 32 == 8 -> conflict-free B frags)
static constexpr int XBATCH    = K_PAD * X_STR;   // 4032 floats per batch tile
static constexpr int XBUF      = BPI * XBATCH;    // 8064 floats per buffer
// A-fragment table: [mh(2)][s(7)][mi(4)][lane(32)][j(4)]  (tf32 bits, frag order)
static constexpr int AFRAG_FLOATS = 2 * 7 * 4 * 32 * 4;       // 7168
static constexpr int X_OFF     = AFRAG_FLOATS;                 // 7168
static constexpr int PSUM_OFF  = X_OFF + 2 * XBUF;             // 23296
static constexpr int SMEM_FLOATS = PSUM_OFF + BPI * D_DIM;     // 23552
static constexpr int SMEM_BYTES  = SMEM_FLOATS * 4;            // 94208 B (2 CTAs fit per SM)

// ---------------------------------------------------------------------------
DEVI uint32_t smem_u32(const void* p) {
    uint32_t a;
    asm("{ .reg .u64 t; cvta.to.shared.u64 t, %1; cvt.u32.u64 %0, t; }" : "=r"(a) : "l"(p));
    return a;
}
DEVI uint32_t f2tf32(float x) {
    uint32_t u;
    asm("cvt.rna.tf32.f32 %0, %1;" : "=r"(u) : "f"(x));
    return u;
}
DEVI void mma16n8k8(float& c0, float& c1, float& c2, float& c3,
                    uint32_t a0, uint32_t a1, uint32_t a2, uint32_t a3,
                    uint32_t b0, uint32_t b1) {
    asm volatile(
        "mma.sync.aligned.m16n8k8.row.col.f32.tf32.tf32.f32 "
        "{%0,%1,%2,%3}, {%4,%5,%6,%7}, {%8,%9}, {%0,%1,%2,%3};"
        : "+f"(c0), "+f"(c1), "+f"(c2), "+f"(c3)
        : "r"(a0), "r"(a1), "r"(a2), "r"(a3), "r"(b0), "r"(b1));
}
DEVI void cp_async16(uint32_t dst, const void* src) {
    asm volatile("cp.async.cg.shared.global [%0], [%1], 16;" :: "r"(dst), "l"(src));
}
DEVI void cp_commit()  { asm volatile("cp.async.commit_group;" ::: "memory"); }
DEVI void cp_wait1()   { asm volatile("cp.async.wait_group 1;" ::: "memory"); }

// Prefetch BPI batches of X into SMEM buffer `buf` (800 16B-chunks per batch)
DEVI void prefetch(uint32_t xs_u32, const float* __restrict__ X, int gi, int buf, int tid) {
    const float* gbase = X + (size_t)gi * BPI * FE;
    const uint32_t dbase = xs_u32 + (uint32_t)(buf * XBUF) * 4u;
#pragma unroll 1
    for (int c = tid; c < BPI * 800; c += NTHREADS) {
        int b   = c / 800;
        int r   = c - b * 800;
        int f   = r >> 4;
        int seg = r & 15;
        const float* src = gbase + b * FE + f * E_DIM + seg * 4;
        uint32_t dst = dbase + (uint32_t)(b * XBATCH + f * X_STR + seg * 4) * 4u;
        cp_async16(dst, src);
    }
}

// ---------------------------------------------------------------------------
__global__ void __launch_bounds__(NTHREADS, 2)
InnerProduct_65429531787441_kernel(const float* __restrict__ X,
                                   const float* __restrict__ Th,
                                   float* __restrict__ out) {
    extern __shared__ float sm[];
    uint32_t* afr = reinterpret_cast<uint32_t*>(sm);          // A-frag table (tf32 bits)
    float*    xs  = sm + X_OFF;                               // X tiles (2 buffers)
    float*    ps  = sm + PSUM_OFF;                            // partial sums [BPI][128]
    const uint32_t xs_u32 = smem_u32(xs);

    const int tid  = threadIdx.x;
    const int lane = tid & 31;
    const int w    = tid >> 5;
    const int b_l  = w >> 2;          // batch slot 0..1
    const int mh   = (w >> 1) & 1;    // d half: 0 -> d 0..63, 1 -> d 64..127
    const int eh   = w & 1;           // e half: 0 -> e 0..31, 1 -> e 32..63
    const int e_base = eh * 32;

    // Prologue prefetch (iteration 0, buffer 0) first, for overlap with init
    int gi0 = blockIdx.x;
    prefetch(xs_u32, X, gi0, 0, tid);
    cp_commit();

    // Build A-fragment table: frag order [mh][s][mi][lane][j], tf32, zero-pad f>=50.
    // Per k-step a thread then reads its 16 A regs as 4 conflict-free LDS.128.
    for (int i = tid; i < AFRAG_FLOATS; i += NTHREADS) {
        int j    = i & 3;
        int ln   = (i >> 2) & 31;
        int mi   = (i >> 7) & 3;
        int t3   = i >> 9;            // mh*7 + s
        int s    = t3 % 7;
        int mhh  = t3 / 7;
        int lg   = ln >> 2, lq = ln & 3;
        int row  = mhh * 64 + mi * 16 + (j & 1) * 8 + lg;
        int f    = 8 * s + lq + (j >> 1) * 4;
        float v  = (f < F_DIM) ? Th[row * F_DIM + f] : 0.f;
        afr[i] = f2tf32(v);
    }
    // Zero-pad X rows f = 50..55 in all 4 batch slots (never overwritten later)
    for (int i = tid; i < 2 * BPI * 6 * X_STR; i += NTHREADS) {
        int slot = i / (6 * X_STR);
        int r    = i - slot * (6 * X_STR);
        xs[slot * XBATCH + F_DIM * X_STR + r] = 0.f;
    }
    __syncthreads();

    const int lg = lane >> 2;   // 0..7
    const int lq = lane & 3;    // 0..3
    // Per-thread A-frag base for this warp's mh (iteration-invariant)
    const uint4* afr4 = reinterpret_cast<const uint4*>(afr) + (mh * 7 * 4 + 0) * 32 + lane;

    int it = 0;
    for (int gi = gi0; gi < NGI; gi += GRID, ++it) {
        const int buf = it & 1;

        // Prefetch next iteration into the other buffer
        if (gi + GRID < NGI) prefetch(xs_u32, X, gi + GRID, buf ^ 1, tid);
        cp_commit();
        cp_wait1();             // current buffer's group complete
        __syncthreads();

        const float* xb = xs + buf * XBUF + b_l * XBATCH;

        float acc[4][4][4];
#pragma unroll
        for (int mi = 0; mi < 4; mi++)
#pragma unroll
            for (int ni = 0; ni < 4; ni++)
#pragma unroll
                for (int j = 0; j < 4; j++) acc[mi][ni][j] = 0.f;

#pragma unroll
        for (int s = 0; s < 7; s++) {
            const int f0 = 8 * s + lq;
            uint4 A[4];
#pragma unroll
            for (int mi = 0; mi < 4; mi++)
                A[mi] = afr4[(s * 4 + mi) * 32];
            uint32_t Bf[4][2];
#pragma unroll
            for (int ni = 0; ni < 4; ni++) {
                const int e = e_base + ni * 8 + lg;
                Bf[ni][0] = f2tf32(xb[f0 * X_STR + e]);
                Bf[ni][1] = f2tf32(xb[(f0 + 4) * X_STR + e]);
            }
#pragma unroll
            for (int mi = 0; mi < 4; mi++)
#pragma unroll
                for (int ni = 0; ni < 4; ni++)
                    mma16n8k8(acc[mi][ni][0], acc[mi][ni][1], acc[mi][ni][2], acc[mi][ni][3],
                              A[mi].x, A[mi].y, A[mi].z, A[mi].w,
                              Bf[ni][0], Bf[ni][1]);
        }

        // Epilogue: sum of squares over this warp's 32 e-columns
        float slo[4], shi[4];
#pragma unroll
        for (int mi = 0; mi < 4; mi++) {
            float a = 0.f, b = 0.f;
#pragma unroll
            for (int ni = 0; ni < 4; ni++) {
                a = fmaf(acc[mi][ni][0], acc[mi][ni][0], a);
                a = fmaf(acc[mi][ni][1], acc[mi][ni][1], a);
                b = fmaf(acc[mi][ni][2], acc[mi][ni][2], b);
                b = fmaf(acc[mi][ni][3], acc[mi][ni][3], b);
            }
            a += __shfl_xor_sync(0xffffffffu, a, 1);
            a += __shfl_xor_sync(0xffffffffu, a, 2);
            b += __shfl_xor_sync(0xffffffffu, b, 1);
            b += __shfl_xor_sync(0xffffffffu, b, 2);
            slo[mi] = a; shi[mi] = b;
        }

        // Combine the two e-halves via SMEM partials, then store
        if (eh == 0 && lq == 0) {
#pragma unroll
            for (int mi = 0; mi < 4; mi++) {
                const int d = mh * 64 + mi * 16 + lg;
                ps[b_l * D_DIM + d]     = slo[mi];
                ps[b_l * D_DIM + d + 8] = shi[mi];
            }
        }
        __syncthreads();
        if (eh == 1 && lq == 0) {
            float* orow = out + (size_t)(gi * BPI + b_l) * D_DIM;
#pragma unroll
            for (int mi = 0; mi < 4; mi++) {
                const int d = mh * 64 + mi * 16 + lg;
                orow[d]     = slo[mi] + ps[b_l * D_DIM + d];
                orow[d + 8] = shi[mi] + ps[b_l * D_DIM + d + 8];
            }
        }
        __syncthreads();   // protect psum + X buffer before next iteration
    }
}

extern "C" void kernel_launch(void* const* d_in, const int* in_sizes, int n_in,
                              void* d_out, int out_size) {
    (void)in_sizes; (void)n_in; (void)out_size;
    const float* X  = (const float*)d_in[0];
    const float* Th = (const float*)d_in[1];
    float* out = (float*)d_out;
    cudaFuncSetAttribute(InnerProduct_65429531787441_kernel,
                         cudaFuncAttributeMaxDynamicSharedMemorySize, SMEM_BYTES);
    InnerProduct_65429531787441_kernel<<<GRID, NTHREADS, SMEM_BYTES>>>(X, Th, out);
}

// round 7
// speedup vs baseline: 2.3190x; 1.3887x over previous
#include <cuda_runtime.h>
#include <cstdint>

#define DEVI __device__ __forceinline__

// Problem constants
static constexpr int B_TOT  = 16384;
static constexpr int F_DIM  = 50;
static constexpr int E_DIM  = 64;
static constexpr int D_DIM  = 128;
static constexpr int FE     = F_DIM * E_DIM;      // 3200 floats per batch

// Kernel config: 2 CTAs/SM, 256 threads (8 warps), 2 batches per CTA-iteration
static constexpr int NTHREADS = 256;
static constexpr int GRID     = 304;
static constexpr int BPI      = 2;
static constexpr int NGI      = B_TOT / BPI;      // 8192

// fp16 GEMM config: K padded to 64 (4 k-steps of 16)
static constexpr int F2_ROWS  = 32;               // k-pairs (f/2), rows 25..31 are zero
static constexpr int F2_REAL  = 25;               // pairs holding real data (f 0..49)
static constexpr int X16_STR  = 72;               // u32 per f2 row (64 + 8 pad -> conflict-free)
static constexpr int X16_BATCH = F2_ROWS * X16_STR;          // 2304 u32
static constexpr int X16_U32   = BPI * X16_BATCH;            // 4608 u32 (18 KB)

// A-frag table: [mq(4)][s(4)][mi(2)][lane(32)][reg(4)] u32 (f16x2, frag order)
static constexpr int AFRAG_U32 = 4 * 4 * 2 * 32 * 4;         // 4096 (16 KB)

// SMEM map (u32 units)
static constexpr int X16_OFF   = AFRAG_U32;                  // 4096
static constexpr int STAGE_OFF = X16_OFF + X16_U32;          // 8704
static constexpr int STAGE_FLOATS = BPI * FE;                // 6400 per buffer
static constexpr int SMEM_U32  = STAGE_OFF + 2 * STAGE_FLOATS; // 21504
static constexpr int SMEM_BYTES = SMEM_U32 * 4;              // 86016 B (2 CTAs/SM fit)

// ---------------------------------------------------------------------------
DEVI uint32_t smem_u32(const void* p) {
    uint32_t a;
    asm("{ .reg .u64 t; cvta.to.shared.u64 t, %1; cvt.u32.u64 %0, t; }" : "=r"(a) : "l"(p));
    return a;
}
// pack two fp32 -> f16x2 (lo in lower half, hi in upper half)
DEVI uint32_t pack_h2(float lo, float hi) {
    uint32_t r;
    asm("cvt.rn.f16x2.f32 %0, %1, %2;" : "=r"(r) : "f"(hi), "f"(lo));
    return r;
}
DEVI void mma16n8k16(float& c0, float& c1, float& c2, float& c3,
                     uint32_t a0, uint32_t a1, uint32_t a2, uint32_t a3,
                     uint32_t b0, uint32_t b1) {
    asm volatile(
        "mma.sync.aligned.m16n8k16.row.col.f32.f16.f16.f32 "
        "{%0,%1,%2,%3}, {%4,%5,%6,%7}, {%8,%9}, {%0,%1,%2,%3};"
        : "+f"(c0), "+f"(c1), "+f"(c2), "+f"(c3)
        : "r"(a0), "r"(a1), "r"(a2), "r"(a3), "r"(b0), "r"(b1));
}
DEVI void cp_async16(uint32_t dst, const void* src) {
    asm volatile("cp.async.cg.shared.global [%0], [%1], 16;" :: "r"(dst), "l"(src));
}
DEVI void cp_commit()  { asm volatile("cp.async.commit_group;" ::: "memory"); }
DEVI void cp_wait1()   { asm volatile("cp.async.wait_group 1;" ::: "memory"); }

// Prefetch one group (2 batches, 6400 contiguous floats) into stage[buf]
DEVI void prefetch(uint32_t stage_u32, const float* __restrict__ X, int gi, int buf, int tid) {
    const float* gbase = X + (size_t)gi * STAGE_FLOATS;
    const uint32_t dbase = stage_u32 + (uint32_t)(buf * STAGE_FLOATS) * 4u;
#pragma unroll 1
    for (int c = tid; c < STAGE_FLOATS / 4; c += NTHREADS)
        cp_async16(dbase + (uint32_t)c * 16u, gbase + c * 4);
}

// ---------------------------------------------------------------------------
__global__ void __launch_bounds__(NTHREADS, 2)
InnerProduct_65429531787441_kernel(const float* __restrict__ X,
                                   const float* __restrict__ Th,
                                   float* __restrict__ out) {
    extern __shared__ uint32_t smu[];
    uint32_t* afr   = smu;                         // A-frag table (f16x2)
    uint32_t* x16   = smu + X16_OFF;               // X fp16 tile [b][f2][e] stride 72
    float*    stage = reinterpret_cast<float*>(smu + STAGE_OFF);  // fp32 staging x2
    const uint32_t stage_u32 = smem_u32(stage);

    const int tid  = threadIdx.x;
    const int lane = tid & 31;
    const int w    = tid >> 5;
    const int b_l  = w >> 2;        // batch slot 0..1
    const int mq   = w & 3;         // d quarter: d in [mq*32, mq*32+32)
    const int lg   = lane >> 2;     // 0..7
    const int lq   = lane & 3;      // 0..3

    // Prologue prefetch (iteration 0 -> stage buffer 0)
    const int gi0 = blockIdx.x;
    prefetch(stage_u32, X, gi0, 0, tid);
    cp_commit();

    // Build A-frag table: Theta fp16 pairs in m16n8k16 fragment order.
    // reg j: j&1 selects row lg / lg+8; j>>1 selects k0 / k0+8. Each u32 packs (k0, k0+1).
    for (int i = tid; i < AFRAG_U32; i += NTHREADS) {
        int j   = i & 3;
        int ln  = (i >> 2) & 31;
        int mi  = (i >> 7) & 1;
        int s   = (i >> 8) & 3;
        int mq_ = i >> 10;
        int lg_ = ln >> 2, lq_ = ln & 3;
        int row = mq_ * 32 + mi * 16 + (j & 1) * 8 + lg_;
        int k0  = 16 * s + 2 * lq_ + (j >> 1) * 8;
        float v0 = (k0     < F_DIM) ? Th[row * F_DIM + k0]     : 0.f;
        float v1 = (k0 + 1 < F_DIM) ? Th[row * F_DIM + k0 + 1] : 0.f;
        afr[i] = pack_h2(v0, v1);
    }
    // Zero the pad f2-rows (25..31) of the fp16 X tile once (never overwritten)
    for (int i = tid; i < BPI * (F2_ROWS - F2_REAL) * X16_STR; i += NTHREADS) {
        int b = i / ((F2_ROWS - F2_REAL) * X16_STR);
        int r = i % ((F2_ROWS - F2_REAL) * X16_STR);
        x16[b * X16_BATCH + F2_REAL * X16_STR + r] = 0u;
    }
    __syncthreads();

    const uint4* afr4 = reinterpret_cast<const uint4*>(afr) + (mq * 8) * 32 + lane;

    int it = 0;
    for (int gi = gi0; gi < NGI; gi += GRID, ++it) {
        const int buf = it & 1;

        // Prefetch next group into the other staging buffer, then wait for current
        if (gi + GRID < NGI) prefetch(stage_u32, X, gi + GRID, buf ^ 1, tid);
        cp_commit();            // (empty group on tail keeps wait semantics correct)
        cp_wait1();
        __syncthreads();        // stage[buf] visible to all threads

        // Convert pass: stage fp32 [b][f][e] -> x16 f16x2 [b][f2][e] (pairs along f)
        {
            const float* stg = stage + buf * STAGE_FLOATS;
#pragma unroll 1
            for (int c = tid; c < BPI * F2_REAL * 16; c += NTHREADS) {
                int b  = c / (F2_REAL * 16);
                int r  = c % (F2_REAL * 16);
                int f2 = r >> 4;
                int e4 = r & 15;
                const float* p0 = stg + b * FE + (2 * f2) * E_DIM + e4 * 4;
                float4 lo = *reinterpret_cast<const float4*>(p0);
                float4 hi = *reinterpret_cast<const float4*>(p0 + E_DIM);
                uint4 q;
                q.x = pack_h2(lo.x, hi.x);
                q.y = pack_h2(lo.y, hi.y);
                q.z = pack_h2(lo.z, hi.z);
                q.w = pack_h2(lo.w, hi.w);
                *reinterpret_cast<uint4*>(x16 + b * X16_BATCH + f2 * X16_STR + e4 * 4) = q;
            }
        }
        __syncthreads();        // x16 ready

        const uint32_t* xb = x16 + b_l * X16_BATCH;

        float acc[2][8][4];
#pragma unroll
        for (int mi = 0; mi < 2; mi++)
#pragma unroll
            for (int ni = 0; ni < 8; ni++)
#pragma unroll
                for (int j = 0; j < 4; j++) acc[mi][ni][j] = 0.f;

#pragma unroll
        for (int s = 0; s < 4; s++) {
            uint4 A0 = afr4[(s * 2 + 0) * 32];
            uint4 A1 = afr4[(s * 2 + 1) * 32];
            const int f2a = 8 * s + lq;          // k0 = 16s + 2lq -> f2 row
            uint32_t Bf[8][2];
#pragma unroll
            for (int ni = 0; ni < 8; ni++) {
                const int e = ni * 8 + lg;
                Bf[ni][0] = xb[f2a * X16_STR + e];
                Bf[ni][1] = xb[(f2a + 4) * X16_STR + e];
            }
#pragma unroll
            for (int ni = 0; ni < 8; ni++) {
                mma16n8k16(acc[0][ni][0], acc[0][ni][1], acc[0][ni][2], acc[0][ni][3],
                           A0.x, A0.y, A0.z, A0.w, Bf[ni][0], Bf[ni][1]);
                mma16n8k16(acc[1][ni][0], acc[1][ni][1], acc[1][ni][2], acc[1][ni][3],
                           A1.x, A1.y, A1.z, A1.w, Bf[ni][0], Bf[ni][1]);
            }
        }

        // Epilogue: warp owns full e-range -> pure shfl reduce + direct store
        float* orow = out + (size_t)(gi * BPI + b_l) * D_DIM;
#pragma unroll
        for (int mi = 0; mi < 2; mi++) {
            float a = 0.f, b = 0.f;
#pragma unroll
            for (int ni = 0; ni < 8; ni++) {
                a = fmaf(acc[mi][ni][0], acc[mi][ni][0], a);
                a = fmaf(acc[mi][ni][1], acc[mi][ni][1], a);
                b = fmaf(acc[mi][ni][2], acc[mi][ni][2], b);
                b = fmaf(acc[mi][ni][3], acc[mi][ni][3], b);
            }
            a += __shfl_xor_sync(0xffffffffu, a, 1);
            a += __shfl_xor_sync(0xffffffffu, a, 2);
            b += __shfl_xor_sync(0xffffffffu, b, 1);
            b += __shfl_xor_sync(0xffffffffu, b, 2);
            if (lq == 0) {
                const int d = mq * 32 + mi * 16 + lg;
                orow[d]     = a;
                orow[d + 8] = b;
            }
        }
        __syncthreads();        // protect x16 (+stage) before next iteration
    }
}

extern "C" void kernel_launch(void* const* d_in, const int* in_sizes, int n_in,
                              void* d_out, int out_size) {
    (void)in_sizes; (void)n_in; (void)out_size;
    const float* X  = (const float*)d_in[0];
    const float* Th = (const float*)d_in[1];
    float* out = (float*)d_out;
    cudaFuncSetAttribute(InnerProduct_65429531787441_kernel,
                         cudaFuncAttributeMaxDynamicSharedMemorySize, SMEM_BYTES);
    InnerProduct_65429531787441_kernel<<<GRID, NTHREADS, SMEM_BYTES>>>(X, Th, out);
}